// round 6
// baseline (speedup 1.0000x reference)
#include <cuda_runtime.h>
#include <cuda_bf16.h>
#include <cfloat>

// Problem constants (S=4096 tokens, D=1024 dim, E=64 experts)
constexpr int S   = 4096;
constexpr int D   = 1024;
constexpr int E   = 64;
constexpr int CAP = 512;          // 2 * ceil(S / (E/4))
// out layout (float32): [0] = l_aux, [1 .. 1+S*E*CAP) = combine, then dispatch

constexpr int NCHAIN = 64;        // gemm+gate blocks (tokens b*64..b*64+63)
constexpr int NB     = 1184;      // total blocks in the fused grid
// slice units: chain/loc blocks (65) get 2u, fill blocks (1119) get 3u
constexpr long long DENOM = 1119LL * 3 + 65LL * 2;   // 3487

// ---------------- scratch (device globals; no allocation allowed) ----------
__device__ float g_logits1[S * E];
__device__ float g_logits2[S * E];
__device__ int   g_expert[S];
__device__ float g_gate[S];
__device__ int   g_loc[S];
__device__ float g_me_part[NCHAIN * E];
__device__ float g_laux;
__device__ int   g_done = 0;      // chain-completion counter (reset each launch)

// ============================================================================
// Fused kernel: fill + gemm + gate + loc, all co-resident in ONE grid.
// ============================================================================
__global__ __launch_bounds__(256, 4) void fused_all(
    const float* __restrict__ A1, const float* __restrict__ A2,
    const float* __restrict__ W1, const float* __restrict__ W2,
    float4* __restrict__ out4, long long n4,
    float* __restrict__ out, long long out_elems)
{
    __shared__ float sA[64 * 32];   // gemm A-tile  (8 KB)  | reused: me-reduce
    __shared__ float sW[64 * 32];   // gemm W-tile  (8 KB)  | reused: l_aux prods
    __shared__ int   sIdx[S];       // loc block only (16 KB)
    __shared__ int   sCnt[4][E];    // loc block only (1 KB)

    const int b    = blockIdx.x;
    const int tid  = threadIdx.x;
    const int lane = tid & 31;
    const int w    = tid >> 5;

    // ---------------- chain blocks: both gemms + gate ----------------------
    if (b < NCHAIN) {
        const int tok0 = b * 64;
        const int tr = tid & 15;         // token quad
        const int ec = tid >> 4;         // expert quad
        // loader mapping: 64 rows x 8 float4-cols per chunk, 2 slots/thread
        const int lrow = tid >> 3;       // 0..31  (and +32)
        const int lc   = tid & 7;        // float4 col 0..7

        for (int p = 0; p < 2; p++) {
            const float* A = p ? A2 : A1;
            const float* W = p ? W2 : W1;
            float* lo      = p ? g_logits2 : g_logits1;

            float acc[4][4];
#pragma unroll
            for (int i = 0; i < 4; i++)
#pragma unroll
                for (int j = 0; j < 4; j++) acc[i][j] = 0.0f;

            float4 pa0, pa1, pw0, pw1;
            pa0 = *(const float4*)&A[(size_t)(tok0 + lrow) * D + lc * 4];
            pa1 = *(const float4*)&A[(size_t)(tok0 + lrow + 32) * D + lc * 4];
            pw0 = *(const float4*)&W[(size_t)lrow * D + lc * 4];
            pw1 = *(const float4*)&W[(size_t)(lrow + 32) * D + lc * 4];

            for (int kt = 0; kt < D; kt += 32) {
                {   // store with XOR swizzle: phys col = lc ^ ((row>>2)&7)
                    int sc0 = (lc ^ ((lrow >> 2) & 7)) * 4;
                    int sc1 = (lc ^ (((lrow + 32) >> 2) & 7)) * 4;
                    *(float4*)&sA[lrow * 32 + sc0]        = pa0;
                    *(float4*)&sA[(lrow + 32) * 32 + sc1] = pa1;
                    *(float4*)&sW[lrow * 32 + sc0]        = pw0;
                    *(float4*)&sW[(lrow + 32) * 32 + sc1] = pw1;
                }
                __syncthreads();

                if (kt + 32 < D) {
                    pa0 = *(const float4*)&A[(size_t)(tok0 + lrow) * D + kt + 32 + lc * 4];
                    pa1 = *(const float4*)&A[(size_t)(tok0 + lrow + 32) * D + kt + 32 + lc * 4];
                    pw0 = *(const float4*)&W[(size_t)lrow * D + kt + 32 + lc * 4];
                    pw1 = *(const float4*)&W[(size_t)(lrow + 32) * D + kt + 32 + lc * 4];
                }

#pragma unroll
                for (int kk = 0; kk < 8; kk++) {
                    float4 av[4], wv[4];
#pragma unroll
                    for (int i = 0; i < 4; i++) {
                        int tok = tr * 4 + i;                    // tok>>2 == tr
                        av[i] = *(const float4*)&sA[tok * 32 + ((kk ^ (tr & 7)) * 4)];
                        int e = ec * 4 + i;                      // e>>2 == ec
                        wv[i] = *(const float4*)&sW[e * 32 + ((kk ^ (ec & 7)) * 4)];
                    }
#pragma unroll
                    for (int i = 0; i < 4; i++)
#pragma unroll
                        for (int j = 0; j < 4; j++) {
                            acc[i][j] += av[i].x * wv[j].x;
                            acc[i][j] += av[i].y * wv[j].y;
                            acc[i][j] += av[i].z * wv[j].z;
                            acc[i][j] += av[i].w * wv[j].w;
                        }
                }
                __syncthreads();
            }
#pragma unroll
            for (int i = 0; i < 4; i++)
                *(float4*)&lo[(size_t)(tok0 + tr * 4 + i) * E + ec * 4] =
                    make_float4(acc[i][0], acc[i][1], acc[i][2], acc[i][3]);
            __syncthreads();   // logits visible to the whole block (global)
        }

        // ---- gate: warp w handles tokens tok0 + w*8 .. +7 ------------------
        float mea = 0.0f, meb = 0.0f;
        for (int r = 0; r < 8; r++) {
            int t = tok0 + w * 8 + r;

            float l1a = g_logits1[(size_t)t * E + lane];
            float l1b = g_logits1[(size_t)t * E + 32 + lane];
            if (lane == 0) l1a = -1e9f;      // expert 0 excluded

            bool sela = false, selb = false;
#pragma unroll 1
            for (int it = 0; it < 16; it++) {
                float va = sela ? -FLT_MAX : l1a;
                float vb = selb ? -FLT_MAX : l1b;
                float v; int idx;
                if (vb > va) { v = vb; idx = lane + 32; } else { v = va; idx = lane; }
#pragma unroll
                for (int off = 16; off > 0; off >>= 1) {
                    float ov = __shfl_xor_sync(0xffffffffu, v, off);
                    int   oi = __shfl_xor_sync(0xffffffffu, idx, off);
                    if (ov > v || (ov == v && oi < idx)) { v = ov; idx = oi; }
                }
                if (idx == lane) sela = true;
                else if (idx == lane + 32) selb = true;
            }

            float l2a = g_logits2[(size_t)t * E + lane];
            float l2b = g_logits2[(size_t)t * E + 32 + lane];
            float va = sela ? l2a : -FLT_MAX;
            float vb = selb ? l2b : -FLT_MAX;
            float m; int ei;
            if (vb > va) { m = vb; ei = lane + 32; } else { m = va; ei = lane; }
#pragma unroll
            for (int off = 16; off > 0; off >>= 1) {
                float ov = __shfl_xor_sync(0xffffffffu, m, off);
                int   oi = __shfl_xor_sync(0xffffffffu, ei, off);
                if (ov > m || (ov == m && oi < ei)) { m = ov; ei = oi; }
            }

            float ea = sela ? expf(l2a - m) : 0.0f;
            float eb = selb ? expf(l2b - m) : 0.0f;
            float ssum = ea + eb;
#pragma unroll
            for (int off = 16; off > 0; off >>= 1)
                ssum += __shfl_xor_sync(0xffffffffu, ssum, off);
            float inv = 1.0f / ssum;

            if (sela) mea += ea * inv;
            if (selb) meb += eb * inv;
            if (lane == 0) { g_expert[t] = ei; g_gate[t] = inv; }
        }

        // ---- me partials (no atomics): block-reduce over 8 warps ----------
        float* sMe = sA;                 // reuse (gemm done)
        sMe[w * 64 + lane]      = mea;
        sMe[w * 64 + 32 + lane] = meb;
        __syncthreads();
        if (tid < 64) {
            float s = 0.0f;
#pragma unroll
            for (int ww = 0; ww < 8; ww++) s += sMe[ww * 64 + tid];
            g_me_part[b * 64 + tid] = s;
        }
        __threadfence();
        __syncthreads();
        if (tid == 0) atomicAdd(&g_done, 1);
    }
    // ---------------- loc block: spin for chain, then cumsum + l_aux -------
    else if (b == NCHAIN) {
        if (tid == 0) { while (atomicAdd(&g_done, 0) < NCHAIN) { } }
        __syncthreads();
        __threadfence();

        for (int i = tid; i < S / 4; i += 256)
            ((int4*)sIdx)[i] = ((const int4*)g_expert)[i];
        __syncthreads();

        const int e = tid & 63, q = tid >> 6;       // 4 quarters of 1024 tokens
        int cnt = 0;
        for (int i = q * 256; i < (q + 1) * 256; i++) {
            int4 v = ((const int4*)sIdx)[i];
            cnt += (v.x == e) + (v.y == e) + (v.z == e) + (v.w == e);
        }
        sCnt[q][e] = cnt;
        __syncthreads();

        int off = 0;
#pragma unroll
        for (int qq = 0; qq < 4; qq++) if (qq < q) off += sCnt[qq][e];
        for (int i = q * 1024; i < (q + 1) * 1024; i += 4) {
            int4 v = *(const int4*)&sIdx[i];
            if (v.x == e) g_loc[i]     = off++;
            if (v.y == e) g_loc[i + 1] = off++;
            if (v.z == e) g_loc[i + 2] = off++;
            if (v.w == e) g_loc[i + 3] = off++;
        }
        __syncthreads();

        if (tid < 64) {
            float me = 0.0f;
            for (int bb = 0; bb < NCHAIN; bb++) me += g_me_part[bb * 64 + tid];
            int ce = sCnt[0][tid] + sCnt[1][tid] + sCnt[2][tid] + sCnt[3][tid];
            sW[tid] = me * (float)ce;     // reuse sW for products
        }
        __syncthreads();
        if (tid == 0) {
            float sum = 0.0f;
            for (int ee = 0; ee < E; ee++) sum += sW[ee];
            g_laux = sum * (1.0f / 65536.0f);  // /(S*S) * E*E / (E/4)
            atomicExch(&g_done, 0);            // reset for next launch
        }
    }

    // ---------------- every block fills its slice of d_out ------------------
    const long long u = n4 / DENOM;
    long long beg, end;
    if (b <= NCHAIN) {                       // late starters: 2u slices
        beg = (long long)b * 2 * u;
        end = beg + 2 * u;
    } else {
        long long f = b - (NCHAIN + 1);
        beg = 130LL * u + f * 3 * u;
        end = (b == NB - 1) ? n4 : beg + 3 * u;
    }
    const float4 z = make_float4(0.f, 0.f, 0.f, 0.f);
    long long i = beg + tid;
    for (; i + 768 < end; i += 1024) {       // 4x STG.128 over a 16KB window
        out4[i]       = z;
        out4[i + 256] = z;
        out4[i + 512] = z;
        out4[i + 768] = z;
    }
    for (; i < end; i += 256) out4[i] = z;
    if (b == NB - 1) {                        // scalar tail (out_size % 4)
        long long t0 = n4 * 4;
        for (long long j = t0 + tid; j < out_elems; j += 256) out[j] = 0.0f;
    }
}

// ---------------- sparse scatter into combine/dispatch + l_aux -------------
__global__ void scatter_kernel(float* __restrict__ out) {
    int s = blockIdx.x * 256 + threadIdx.x;
    if (s == 0) out[0] = g_laux;
    if (s >= S) return;
    int loc = g_loc[s];
    if (loc >= CAP) return;            // dropped token: everything stays 0
    size_t off = ((size_t)s * E + g_expert[s]) * CAP + loc;
    out[1 + off] = g_gate[s];
    out[1 + (size_t)S * E * CAP + off] = 1.0f;
}

// ---------------- launch ----------------------------------------------------
extern "C" void kernel_launch(void* const* d_in, const int* in_sizes, int n_in,
                              void* d_out, int out_size) {
    const float* input1 = (const float*)d_in[0];
    const float* input2 = (const float*)d_in[1];
    const float* wg1    = (const float*)d_in[2];
    const float* wg2    = (const float*)d_in[3];
    float* out = (float*)d_out;

    const long long n4 = (long long)out_size / 4;

    fused_all<<<NB, 256>>>(input1, input2, wg1, wg2,
                           (float4*)out, n4, out, (long long)out_size);
    scatter_kernel<<<(S + 255) / 256, 256>>>(out);
}

// round 8
// speedup vs baseline: 1.7628x; 1.7628x over previous
#include <cuda_runtime.h>
#include <cuda_bf16.h>
#include <cfloat>

// Problem constants (S=4096 tokens, D=1024 dim, E=64 experts)
constexpr int S   = 4096;
constexpr int D   = 1024;
constexpr int E   = 64;
constexpr int CAP = 512;          // 2 * ceil(S / (E/4))
constexpr int KSLICES = 4;        // split-K factor (K-slice = 256)
constexpr int KS      = D / KSLICES;
constexpr int NGATE   = S / 8;    // gate blocks (8 tokens each)
// out layout (float32): [0] = l_aux, [1 .. 1+S*E*CAP) = combine, then dispatch

// ---------------- scratch (device globals; no allocation allowed) ----------
__device__ float g_part[2 * KSLICES * S * E];    // split-K partial logits (8MB)
__device__ int   g_expert[S];
__device__ float g_gate[S];
__device__ int   g_loc[S];
__device__ float g_me_part[NGATE * E];           // per-gate-block me partials
__device__ float g_laux;

// ---------------- side stream + events (R2-proven pattern) -----------------
static cudaStream_t g_s1 = nullptr;
static cudaEvent_t  g_evFork = nullptr, g_evJoin = nullptr;
namespace {
struct StreamInit {
    StreamInit() {
        if (cudaStreamCreateWithFlags(&g_s1, cudaStreamNonBlocking) != cudaSuccess)
            g_s1 = nullptr;
        if (cudaEventCreateWithFlags(&g_evFork, cudaEventDisableTiming) != cudaSuccess)
            g_evFork = nullptr;
        if (cudaEventCreateWithFlags(&g_evJoin, cudaEventDisableTiming) != cudaSuccess)
            g_evJoin = nullptr;
    }
};
static StreamInit g_streamInit;
}

// ---------------- split-K GEMM: partial logits = X @ W^T -------------------
// grid (64 tok-tiles, 2 gemms, 4 K-slices). Tile 64x64, K-chunks of 64.
// Same proven smem XOR-swizzle scheme as the 210us kernel.
__global__ __launch_bounds__(256) void gemm_kernel(
    const float* __restrict__ A1, const float* __restrict__ A2,
    const float* __restrict__ W1, const float* __restrict__ W2)
{
    const float* A = blockIdx.y ? A2 : A1;
    const float* W = blockIdx.y ? W2 : W1;
    float* out = g_part + ((size_t)(blockIdx.y * KSLICES + blockIdx.z)) * S * E;
    const int tok0 = blockIdx.x * 64;
    const int kt0  = blockIdx.z * KS;

    __shared__ float As[64 * 64];
    __shared__ float Ws[64 * 64];

    const int tid = threadIdx.x;
    const int lr  = tid >> 4;   // loader row base (0..15)
    const int lc  = tid & 15;   // loader float4 column (0..15)
    const int tr  = tid & 15;   // compute: token quad
    const int ec  = tid >> 4;   // compute: expert quad

    float acc[4][4];
#pragma unroll
    for (int i = 0; i < 4; i++)
#pragma unroll
        for (int j = 0; j < 4; j++) acc[i][j] = 0.0f;

    float4 pa[4], pw[4];
#pragma unroll
    for (int p = 0; p < 4; p++) {
        int row = lr + p * 16;
        pa[p] = *(const float4*)&A[(size_t)(tok0 + row) * D + kt0 + lc * 4];
        pw[p] = *(const float4*)&W[(size_t)row * D + kt0 + lc * 4];
    }

    for (int kt = kt0; kt < kt0 + KS; kt += 64) {
#pragma unroll
        for (int p = 0; p < 4; p++) {
            int row = lr + p * 16;
            int sc  = (lc ^ ((row >> 2) & 7)) * 4;
            *(float4*)&As[row * 64 + sc] = pa[p];
            *(float4*)&Ws[row * 64 + sc] = pw[p];
        }
        __syncthreads();

        if (kt + 64 < kt0 + KS) {
#pragma unroll
            for (int p = 0; p < 4; p++) {
                int row = lr + p * 16;
                pa[p] = *(const float4*)&A[(size_t)(tok0 + row) * D + kt + 64 + lc * 4];
                pw[p] = *(const float4*)&W[(size_t)row * D + kt + 64 + lc * 4];
            }
        }

#pragma unroll
        for (int kk = 0; kk < 16; kk++) {
            float4 av[4], wv[4];
#pragma unroll
            for (int i = 0; i < 4; i++) {
                int tok = tr * 4 + i;
                av[i] = *(const float4*)&As[tok * 64 + ((kk ^ (tr & 7)) * 4)];
                int e = ec * 4 + i;
                wv[i] = *(const float4*)&Ws[e * 64 + ((kk ^ (ec & 7)) * 4)];
            }
#pragma unroll
            for (int i = 0; i < 4; i++)
#pragma unroll
                for (int j = 0; j < 4; j++) {
                    acc[i][j] += av[i].x * wv[j].x;
                    acc[i][j] += av[i].y * wv[j].y;
                    acc[i][j] += av[i].z * wv[j].z;
                    acc[i][j] += av[i].w * wv[j].w;
                }
        }
        __syncthreads();
    }

#pragma unroll
    for (int i = 0; i < 4; i++)
        *(float4*)&out[(size_t)(tok0 + tr * 4 + i) * E + ec * 4] =
            make_float4(acc[i][0], acc[i][1], acc[i][2], acc[i][3]);
}

// ---------------- gating: warp per token, sums split-K partials ------------
__global__ __launch_bounds__(256) void gate_kernel() {
    __shared__ float sMe[8 * 64];
    const int b    = blockIdx.x;
    const int tid  = threadIdx.x;
    const int lane = tid & 31;
    const int w    = tid >> 5;
    const int t    = b * 8 + w;

    // ---- reduce split-K partials: l1 (group logits), l2 (expert logits)
    float l1a = 0.f, l1b = 0.f, l2a = 0.f, l2b = 0.f;
#pragma unroll
    for (int kz = 0; kz < KSLICES; kz++) {
        const float* p1 = g_part + (size_t)kz * S * E + (size_t)t * E;
        const float* p2 = g_part + (size_t)(KSLICES + kz) * S * E + (size_t)t * E;
        l1a += p1[lane];  l1b += p1[32 + lane];
        l2a += p2[lane];  l2b += p2[32 + lane];
    }
    if (lane == 0) l1a = -1e9f;      // expert 0 excluded from group gating

    // ---- stage 1: top-16 of group logits (softmax monotone -> skip it)
    bool sela = false, selb = false;
#pragma unroll 1
    for (int it = 0; it < 16; it++) {
        float va = sela ? -FLT_MAX : l1a;
        float vb = selb ? -FLT_MAX : l1b;
        float v; int idx;
        if (vb > va) { v = vb; idx = lane + 32; } else { v = va; idx = lane; }
#pragma unroll
        for (int off = 16; off > 0; off >>= 1) {
            float ov = __shfl_xor_sync(0xffffffffu, v, off);
            int   oi = __shfl_xor_sync(0xffffffffu, idx, off);
            if (ov > v || (ov == v && oi < idx)) { v = ov; idx = oi; }
        }
        if (idx == lane) sela = true;
        else if (idx == lane + 32) selb = true;
    }

    // ---- stage 2: masked softmax over the 16 selected experts
    float va = sela ? l2a : -FLT_MAX;
    float vb = selb ? l2b : -FLT_MAX;
    float m; int ei;
    if (vb > va) { m = vb; ei = lane + 32; } else { m = va; ei = lane; }
#pragma unroll
    for (int off = 16; off > 0; off >>= 1) {
        float ov = __shfl_xor_sync(0xffffffffu, m, off);
        int   oi = __shfl_xor_sync(0xffffffffu, ei, off);
        if (ov > m || (ov == m && oi < ei)) { m = ov; ei = oi; }
    }

    float ea = sela ? expf(l2a - m) : 0.0f;
    float eb = selb ? expf(l2b - m) : 0.0f;
    float ssum = ea + eb;
#pragma unroll
    for (int off = 16; off > 0; off >>= 1)
        ssum += __shfl_xor_sync(0xffffffffu, ssum, off);
    float inv = 1.0f / ssum;

    if (lane == 0) { g_expert[t] = ei; g_gate[t] = inv; }

    // ---- per-block me partials (no atomics)
    sMe[w * 64 + lane]      = sela ? ea * inv : 0.0f;
    sMe[w * 64 + 32 + lane] = selb ? eb * inv : 0.0f;
    __syncthreads();
    if (tid < 64) {
        float s = 0.0f;
#pragma unroll
        for (int ww = 0; ww < 8; ww++) s += sMe[ww * 64 + tid];
        g_me_part[b * 64 + tid] = s;
    }
}

// ---------------- locations via match.any ballots + l_aux ------------------
// Single block, 1024 threads (32 warps). Warp handles 4 windows of 32 tokens.
// rank(token) = exclusive-scan over windows of per-expert counts + in-window
// rank from the match mask.
__global__ __launch_bounds__(1024) void loc_kernel() {
    __shared__ int   sCnt[128][E];     // per-window per-expert counts (32 KB)
    __shared__ float sPart[16][E];     // me reduction staging (4 KB)
    __shared__ float sMe[E];

    const int tid  = threadIdx.x;
    const int lane = tid & 31;
    const int wp   = tid >> 5;         // warp id 0..31

    for (int i = tid; i < 128 * E; i += 1024) ((int*)sCnt)[i] = 0;
    __syncthreads();

    int   eReg[4];
    unsigned mReg[4];
#pragma unroll
    for (int k = 0; k < 4; k++) {
        int win = wp + k * 32;
        int e   = g_expert[win * 32 + lane];
        unsigned mask = __match_any_sync(0xffffffffu, e);
        eReg[k] = e; mReg[k] = mask;
        if ((mask & ((1u << lane) - 1)) == 0)     // leader lane of group
            sCnt[win][e] = __popc(mask);
    }

    // me partial reduction: thread (i = tid>>6, e = tid&63) sums 32 blocks
    {
        int e = tid & 63, i = tid >> 6;
        float s = 0.0f;
        for (int b = i * 32; b < (i + 1) * 32; b++) s += g_me_part[b * 64 + e];
        sPart[i][e] = s;
    }
    __syncthreads();

    // exclusive scan over 128 windows per expert; ce = total count
    if (tid < 64) {
        int run = 0;
#pragma unroll 4
        for (int win = 0; win < 128; win++) {
            int c = sCnt[win][tid];
            sCnt[win][tid] = run;
            run += c;
        }
        float me = 0.0f;
#pragma unroll
        for (int i = 0; i < 16; i++) me += sPart[i][tid];
        sMe[tid] = me * (float)run;
    }
    __syncthreads();

#pragma unroll
    for (int k = 0; k < 4; k++) {
        int win  = wp + k * 32;
        int rank = sCnt[win][eReg[k]] + __popc(mReg[k] & ((1u << lane) - 1));
        g_loc[win * 32 + lane] = rank;
    }

    if (tid == 0) {
        float sum = 0.0f;
        for (int ee = 0; ee < E; ee++) sum += sMe[ee];
        g_laux = sum * (1.0f / 65536.0f);   // sum(me*ce)/(S*S)/num_2nd*E*E
    }
}

// ---------------- sparse scatter into combine/dispatch + l_aux -------------
__global__ void scatter_kernel(float* __restrict__ out) {
    int s = blockIdx.x * 256 + threadIdx.x;
    if (s == 0) out[0] = g_laux;
    if (s >= S) return;
    int loc = g_loc[s];
    if (loc >= CAP) return;            // dropped token: everything stays 0
    size_t off = ((size_t)s * E + g_expert[s]) * CAP + loc;
    out[1 + off] = g_gate[s];
    out[1 + (size_t)S * E * CAP + off] = 1.0f;
}

// ---------------- launch ----------------------------------------------------
extern "C" void kernel_launch(void* const* d_in, const int* in_sizes, int n_in,
                              void* d_out, int out_size) {
    const float* input1 = (const float*)d_in[0];
    const float* input2 = (const float*)d_in[1];
    const float* wg1    = (const float*)d_in[2];
    const float* wg2    = (const float*)d_in[3];
    float* out = (float*)d_out;

    dim3 g(S / 64, 2, KSLICES);
    const bool forked = (g_s1 && g_evFork && g_evJoin);

    if (forked) {
        // Fork: compute chain on side stream, concurrent with the big memset.
        cudaEventRecord(g_evFork, 0);
        cudaStreamWaitEvent(g_s1, g_evFork, 0);

        gemm_kernel<<<g, 256, 0, g_s1>>>(input1, input2, wg1, wg2);
        gate_kernel<<<NGATE, 256, 0, g_s1>>>();
        loc_kernel<<<1, 1024, 0, g_s1>>>();
        cudaEventRecord(g_evJoin, g_s1);

        // Dominant cost: zero 1.07 GB of poisoned output (driver memset).
        cudaMemsetAsync(d_out, 0, (size_t)out_size * sizeof(float), 0);

        // Join, then sparse scatter into the zeroed buffer.
        cudaStreamWaitEvent(0, g_evJoin, 0);
        scatter_kernel<<<(S + 255) / 256, 256>>>(out);
    } else {
        // Fallback: fully serial on the captured stream.
        cudaMemsetAsync(d_out, 0, (size_t)out_size * sizeof(float), 0);
        gemm_kernel<<<g, 256>>>(input1, input2, wg1, wg2);
        gate_kernel<<<NGATE, 256>>>();
        loc_kernel<<<1, 1024>>>();
        scatter_kernel<<<(S + 255) / 256, 256>>>(out);
    }
}